// round 1
// baseline (speedup 1.0000x reference)
#include <cuda_runtime.h>
#include <cuda_bf16.h>

// ROI align 2.5D — separable-weight formulation.
// fea: (B=16, C=64, H=128, W=128, D=8) f32, contiguous.
// keypoints: (16, 5, 3) f32.
// out: (16, 5, 64, 2, 2, 8) f32.
//
// Per (ROI, bin): out[c,d] = (1/(gh*gw)) * sum_y Wy[y] * sum_x Wx[x] * fea[b,c,y,x,d]
// where Wy/Wx are per-axis weight vectors obtained by scattering each adaptive
// grid sample's bilinear fractions onto its two adjacent rows/cols.

#define RB  16
#define RC  64
#define RH  128
#define RW  128
#define RD  8
#define NKP 5
#define NROI (RB * NKP)          // 80
#define CROP 16.0f               // H * 1/8
#define WSLOTS 24                // max distinct cols/rows per bin window (<=18)

__global__ __launch_bounds__(64)
void roi_align_25d_kernel(const float* __restrict__ fea,
                          const float* __restrict__ kp,
                          float* __restrict__ out) {
    const int blk = blockIdx.x;          // 640 blocks
    const int cg  = blk & 1;             // channel half
    const int bin = (blk >> 1) & 3;      // ph*2 + pw
    const int n   = blk >> 3;            // ROI index 0..79
    const int ph  = bin >> 1;
    const int pw  = bin & 1;
    const int b   = n / NKP;

    __shared__ float Wx[WSLOTS], Wy[WSLOTS];
    __shared__ int   sBase[2];   // [0]=x0, [1]=y0
    __shared__ int   sCnt[2];    // [0]=nx, [1]=ny
    __shared__ int   sG[2];      // [0]=gw, [1]=gh

    const int t = threadIdx.x;

    if (t < 2) {
        // t==0 -> x axis (uses pw), t==1 -> y axis (uses ph)
        float coord = kp[n * 3 + t] * 128.0f;
        float mn = fminf(fmaxf(coord - CROP, 0.0f), 127.0f);
        float mx = fminf(fmaxf(coord + CROP, 0.0f), 127.0f);
        float roi = fmaxf(mx - mn, 1.0f);
        float bin_sz = roi * 0.5f;                 // roi / P (P=2)
        int   g = (int)ceilf(bin_sz);              // ceil(roi/2), 1..16
        float step = bin_sz / (float)g;
        int   p = (t == 0) ? pw : ph;
        float start = mn + (float)p * bin_sz;

        float* Wp = (t == 0) ? Wx : Wy;
        #pragma unroll
        for (int i = 0; i < WSLOTS; i++) Wp[i] = 0.0f;

        // first sample defines the base index (samples are monotone in g)
        float s0 = start + 0.5f * step;
        int base = (int)floorf(fmaxf(s0, 0.0f));
        if (base > 127) base = 127;
        int maxc = base;

        for (int gi = 0; gi < g; gi++) {
            float s = start + ((float)gi + 0.5f) * step;
            if (s < -1.0f || s > 128.0f) continue;     // validity mask
            float c0 = fmaxf(s, 0.0f);
            int l0 = (int)floorf(c0);
            int lo, hi; float fr;
            if (l0 >= 127) { lo = 127; hi = 127; fr = 0.0f; }
            else           { lo = l0;  hi = l0 + 1; fr = c0 - (float)l0; }
            Wp[lo - base] += 1.0f - fr;
            Wp[hi - base] += fr;
            if (hi > maxc) maxc = hi;
        }
        sBase[t] = base;
        sCnt[t]  = maxc - base + 1;
        sG[t]    = g;
    }
    __syncthreads();

    const int x0 = sBase[0], nx = sCnt[0];
    const int y0 = sBase[1], ny = sCnt[1];
    const float inv = 1.0f / ((float)sG[0] * (float)sG[1]);

    const int c  = cg * 32 + (t >> 1);
    const int dq = t & 1;                // which float4 of the 8-float depth

    const float4* __restrict__ fp = (const float4*)fea;
    // float4 index: (((b*C + c)*H + y)*W + x) * 2 + dq
    const long long chanBase = ((long long)(b * RC + c)) * RH;

    float4 acc = make_float4(0.f, 0.f, 0.f, 0.f);

    for (int iy = 0; iy < ny; iy++) {
        const float wy = Wy[iy];
        const float4* rowp = fp + ((chanBase + (y0 + iy)) * RW + x0) * 2 + dq;
        float4 racc = make_float4(0.f, 0.f, 0.f, 0.f);
        #pragma unroll 4
        for (int ix = 0; ix < nx; ix++) {
            const float wxv = Wx[ix];
            const float4 v = rowp[(long long)ix * 2];
            racc.x += wxv * v.x;
            racc.y += wxv * v.y;
            racc.z += wxv * v.z;
            racc.w += wxv * v.w;
        }
        acc.x += wy * racc.x;
        acc.y += wy * racc.y;
        acc.z += wy * racc.z;
        acc.w += wy * racc.w;
    }

    acc.x *= inv; acc.y *= inv; acc.z *= inv; acc.w *= inv;

    // out: (NROI, C, 2, 2, 8) -> float4 index (((n*C + c)*2 + ph)*2 + pw)*2 + dq
    float4* __restrict__ op = (float4*)out;
    op[((((long long)n * RC + c) * 2 + ph) * 2 + pw) * 2 + dq] = acc;
}

extern "C" void kernel_launch(void* const* d_in, const int* in_sizes, int n_in,
                              void* d_out, int out_size) {
    const float* fea = (const float*)d_in[0];
    const float* kp  = (const float*)d_in[1];
    float* out = (float*)d_out;
    (void)in_sizes; (void)n_in; (void)out_size;

    dim3 grid(NROI * 4 * 2);   // 640 blocks: ROI x bin x channel-half
    dim3 block(64);            // 32 channels x 2 float4-depth-quads
    roi_align_25d_kernel<<<grid, block>>>(fea, kp, out);
}

// round 4
// speedup vs baseline: 1.9000x; 1.9000x over previous
#include <cuda_runtime.h>
#include <cuda_bf16.h>

// ROI align 2.5D — separable-weight formulation, 4-way row-split per block.
// fea: (B=16, C=64, H=128, W=128, D=8) f32, contiguous.
// keypoints: (16, 5, 3) f32.
// out: (16, 5, 64, 2, 2, 8) f32.
//
// Per (ROI, bin): out[c,d] = (1/(gh*gw)) * sum_y Wy[y] * sum_x Wx[x] * fea[b,c,y,x,d]
// Block = one (ROI, bin). 512 threads = 4 row-groups x 64 channels x 2 depth-quads.
// Each row-group accumulates rows iy = ys, ys+4, ...; partials reduced in shared.

#define RB  16
#define RC  64
#define RH  128
#define RW  128
#define RD  8
#define NKP 5
#define NROI (RB * NKP)          // 80
#define CROP 16.0f               // H * 1/8
#define WSLOTS 24                // max distinct cols/rows per bin window (<=18)
#define YS  4                    // row-split factor

__global__ __launch_bounds__(512)
void roi_align_25d_kernel(const float* __restrict__ fea,
                          const float* __restrict__ kp,
                          float* __restrict__ out) {
    const int blk = blockIdx.x;          // 320 blocks: ROI x bin
    const int bin = blk & 3;             // ph*2 + pw
    const int n   = blk >> 2;            // ROI index 0..79
    const int ph  = bin >> 1;
    const int pw  = bin & 1;
    const int b   = n / NKP;

    __shared__ float Wx[WSLOTS], Wy[WSLOTS];
    __shared__ int   sBase[2];   // [0]=x0, [1]=y0
    __shared__ int   sCnt[2];    // [0]=nx, [1]=ny
    __shared__ int   sG[2];      // [0]=gw, [1]=gh
    __shared__ float4 part[YS][128];

    const int t  = threadIdx.x;
    const int ys = t >> 7;               // row group 0..3
    const int r  = t & 127;              // c*2 + dq

    if (t < 2) {
        // t==0 -> x axis (uses pw), t==1 -> y axis (uses ph)
        float coord = kp[n * 3 + t] * 128.0f;
        float mn = fminf(fmaxf(coord - CROP, 0.0f), 127.0f);
        float mx = fminf(fmaxf(coord + CROP, 0.0f), 127.0f);
        float roi = fmaxf(mx - mn, 1.0f);
        float bin_sz = roi * 0.5f;                 // roi / P (P=2)
        int   g = (int)ceilf(bin_sz);              // ceil(roi/2), 1..16
        float step = bin_sz / (float)g;
        int   p = (t == 0) ? pw : ph;
        float start = mn + (float)p * bin_sz;

        float* Wp = (t == 0) ? Wx : Wy;
        #pragma unroll
        for (int i = 0; i < WSLOTS; i++) Wp[i] = 0.0f;

        // first sample defines the base index (samples are monotone in g)
        float s0 = start + 0.5f * step;
        int base = (int)floorf(fmaxf(s0, 0.0f));
        if (base > 127) base = 127;
        int maxc = base;

        for (int gi = 0; gi < g; gi++) {
            float s = start + ((float)gi + 0.5f) * step;
            if (s < -1.0f || s > 128.0f) continue;     // validity mask
            float c0 = fmaxf(s, 0.0f);
            int l0 = (int)floorf(c0);
            int lo, hi; float fr;
            if (l0 >= 127) { lo = 127; hi = 127; fr = 0.0f; }
            else           { lo = l0;  hi = l0 + 1; fr = c0 - (float)l0; }
            Wp[lo - base] += 1.0f - fr;
            Wp[hi - base] += fr;
            if (hi > maxc) maxc = hi;
        }
        sBase[t] = base;
        sCnt[t]  = maxc - base + 1;
        sG[t]    = g;
    }
    __syncthreads();

    const int x0 = sBase[0], nx = sCnt[0];
    const int y0 = sBase[1], ny = sCnt[1];
    const float inv = 1.0f / ((float)sG[0] * (float)sG[1]);

    const int c  = r >> 1;
    const int dq = r & 1;                // which float4 of the 8-float depth

    const float4* __restrict__ fp = (const float4*)fea;
    // float4 index: (((b*C + c)*H + y)*W + x) * 2 + dq   (fits in int: <2^25)
    const int chanBase = (b * RC + c) * RH;

    float4 acc = make_float4(0.f, 0.f, 0.f, 0.f);

    for (int iy = ys; iy < ny; iy += YS) {
        const float wy = Wy[iy];
        const float4* rowp = fp + ((chanBase + (y0 + iy)) * RW + x0) * 2 + dq;
        float4 racc = make_float4(0.f, 0.f, 0.f, 0.f);
        #pragma unroll 4
        for (int ix = 0; ix < nx; ix++) {
            const float wxv = Wx[ix];
            const float4 v = rowp[ix * 2];
            racc.x += wxv * v.x;
            racc.y += wxv * v.y;
            racc.z += wxv * v.z;
            racc.w += wxv * v.w;
        }
        acc.x += wy * racc.x;
        acc.y += wy * racc.y;
        acc.z += wy * racc.z;
        acc.w += wy * racc.w;
    }

    part[ys][r] = acc;
    __syncthreads();

    if (t < 128) {
        float4 a0 = part[0][t];
        float4 a1 = part[1][t];
        float4 a2 = part[2][t];
        float4 a3 = part[3][t];
        float4 s;
        s.x = ((a0.x + a1.x) + (a2.x + a3.x)) * inv;
        s.y = ((a0.y + a1.y) + (a2.y + a3.y)) * inv;
        s.z = ((a0.z + a1.z) + (a2.z + a3.z)) * inv;
        s.w = ((a0.w + a1.w) + (a2.w + a3.w)) * inv;

        // out: (NROI, C, 2, 2, 8) -> float4 index (((n*C + c)*2 + ph)*2 + pw)*2 + dq
        float4* __restrict__ op = (float4*)out;
        const int cc = t >> 1, dd = t & 1;
        op[(((n * RC + cc) * 2 + ph) * 2 + pw) * 2 + dd] = s;
    }
}

extern "C" void kernel_launch(void* const* d_in, const int* in_sizes, int n_in,
                              void* d_out, int out_size) {
    const float* fea = (const float*)d_in[0];
    const float* kp  = (const float*)d_in[1];
    float* out = (float*)d_out;
    (void)in_sizes; (void)n_in; (void)out_size;

    dim3 grid(NROI * 4);       // 320 blocks: ROI x bin
    dim3 block(512);           // 4 row-groups x 64 channels x 2 float4-depth-quads
    roi_align_25d_kernel<<<grid, block>>>(fea, kp, out);
}

// round 5
// speedup vs baseline: 2.1587x; 1.1362x over previous
#include <cuda_runtime.h>
#include <cuda_bf16.h>

// ROI align 2.5D — separable-weight formulation.
// fea: (B=16, C=64, H=128, W=128, D=8) f32, contiguous.
// keypoints: (16, 5, 3) f32.
// out: (16, 5, 64, 2, 2, 8) f32.
//
// Per (ROI, bin): out[c,d] = (1/(gh*gw)) * sum_y Wy[y] * sum_x Wx[x] * fea[b,c,y,x,d]
//
// R5: fine-grained blocks for load balance + row-pair interleave for MLP.
// Block = (ROI, bin, channel-group of 16). 128 threads = 4 ygroups x 16ch x 2 dq.
// Each thread accumulates TWO rows per x-sweep (iy, iy+4) -> 8 loads in flight.

#define RB  16
#define RC  64
#define RH  128
#define RW  128
#define RD  8
#define NKP 5
#define NROI (RB * NKP)          // 80
#define CROP 16.0f               // H * 1/8
#define WSLOTS 24                // max distinct cols/rows per bin window (<=18)
#define YS  4                    // row-split factor

__global__ __launch_bounds__(128)
void roi_align_25d_kernel(const float* __restrict__ fea,
                          const float* __restrict__ kp,
                          float* __restrict__ out) {
    const int blk = blockIdx.x;          // 1280 blocks: ROI x bin x cg
    const int cg  = blk & 3;             // channel group (16 ch)
    const int bin = (blk >> 2) & 3;      // ph*2 + pw
    const int n   = blk >> 4;            // ROI index 0..79
    const int ph  = bin >> 1;
    const int pw  = bin & 1;
    const int b   = n / NKP;

    __shared__ float Wx[WSLOTS], Wy[WSLOTS];
    __shared__ int   sBase[2];   // [0]=x0, [1]=y0
    __shared__ int   sCnt[2];    // [0]=nx, [1]=ny
    __shared__ int   sG[2];      // [0]=gw, [1]=gh
    __shared__ float4 part[YS][32];

    const int t  = threadIdx.x;
    const int ys = t >> 5;               // row group 0..3
    const int r  = t & 31;               // (c_in_group)*2 + dq

    if (t < 2) {
        // t==0 -> x axis (uses pw), t==1 -> y axis (uses ph)
        float coord = kp[n * 3 + t] * 128.0f;
        float mn = fminf(fmaxf(coord - CROP, 0.0f), 127.0f);
        float mx = fminf(fmaxf(coord + CROP, 0.0f), 127.0f);
        float roi = fmaxf(mx - mn, 1.0f);
        float bin_sz = roi * 0.5f;                 // roi / P (P=2)
        int   g = (int)ceilf(bin_sz);              // ceil(roi/2), 1..16
        float step = bin_sz / (float)g;
        int   p = (t == 0) ? pw : ph;
        float start = mn + (float)p * bin_sz;

        float* Wp = (t == 0) ? Wx : Wy;
        #pragma unroll
        for (int i = 0; i < WSLOTS; i++) Wp[i] = 0.0f;

        // first sample defines the base index (samples are monotone in g)
        float s0 = start + 0.5f * step;
        int base = (int)floorf(fmaxf(s0, 0.0f));
        if (base > 127) base = 127;
        int maxc = base;

        for (int gi = 0; gi < g; gi++) {
            float s = start + ((float)gi + 0.5f) * step;
            if (s < -1.0f || s > 128.0f) continue;     // validity mask
            float c0 = fmaxf(s, 0.0f);
            int l0 = (int)floorf(c0);
            int lo, hi; float fr;
            if (l0 >= 127) { lo = 127; hi = 127; fr = 0.0f; }
            else           { lo = l0;  hi = l0 + 1; fr = c0 - (float)l0; }
            Wp[lo - base] += 1.0f - fr;
            Wp[hi - base] += fr;
            if (hi > maxc) maxc = hi;
        }
        sBase[t] = base;
        sCnt[t]  = maxc - base + 1;
        sG[t]    = g;
    }
    __syncthreads();

    const int x0 = sBase[0], nx = sCnt[0];
    const int y0 = sBase[1], ny = sCnt[1];
    const float inv = 1.0f / ((float)sG[0] * (float)sG[1]);

    const int c  = cg * 16 + (r >> 1);
    const int dq = r & 1;                // which float4 of the 8-float depth

    const float4* __restrict__ fp = (const float4*)fea;
    // float4 index: (((b*C + c)*H + y)*W + x) * 2 + dq   (fits in int: <2^25)
    const int chanBase = (b * RC + c) * RH;

    float4 acc = make_float4(0.f, 0.f, 0.f, 0.f);

    // Two rows per sweep: iy and iy+YS, 8 float4 loads in flight.
    for (int iy = ys; iy < ny; iy += 2 * YS) {
        const int iy2 = iy + YS;
        const bool h2 = (iy2 < ny);
        const float wy0 = Wy[iy];
        const float wy1 = h2 ? Wy[iy2] : 0.0f;
        const float4* r0 = fp + ((chanBase + (y0 + iy)) * RW + x0) * 2 + dq;
        const float4* r1 = h2 ? fp + ((chanBase + (y0 + iy2)) * RW + x0) * 2 + dq
                              : r0;   // duplicate -> L1 hit, weight 0
        float4 a0 = make_float4(0.f, 0.f, 0.f, 0.f);
        float4 a1 = make_float4(0.f, 0.f, 0.f, 0.f);
        #pragma unroll 4
        for (int ix = 0; ix < nx; ix++) {
            const float wxv = Wx[ix];
            const float4 v0 = r0[ix * 2];
            const float4 v1 = r1[ix * 2];
            a0.x += wxv * v0.x;  a0.y += wxv * v0.y;
            a0.z += wxv * v0.z;  a0.w += wxv * v0.w;
            a1.x += wxv * v1.x;  a1.y += wxv * v1.y;
            a1.z += wxv * v1.z;  a1.w += wxv * v1.w;
        }
        acc.x += wy0 * a0.x + wy1 * a1.x;
        acc.y += wy0 * a0.y + wy1 * a1.y;
        acc.z += wy0 * a0.z + wy1 * a1.z;
        acc.w += wy0 * a0.w + wy1 * a1.w;
    }

    part[ys][r] = acc;
    __syncthreads();

    if (t < 32) {
        float4 a0 = part[0][t];
        float4 a1 = part[1][t];
        float4 a2 = part[2][t];
        float4 a3 = part[3][t];
        float4 s;
        s.x = ((a0.x + a1.x) + (a2.x + a3.x)) * inv;
        s.y = ((a0.y + a1.y) + (a2.y + a3.y)) * inv;
        s.z = ((a0.z + a1.z) + (a2.z + a3.z)) * inv;
        s.w = ((a0.w + a1.w) + (a2.w + a3.w)) * inv;

        // out: (NROI, C, 2, 2, 8) -> float4 index (((n*C + c)*2 + ph)*2 + pw)*2 + dq
        float4* __restrict__ op = (float4*)out;
        const int cc = cg * 16 + (t >> 1), dd = t & 1;
        op[(((n * RC + cc) * 2 + ph) * 2 + pw) * 2 + dd] = s;
    }
}

extern "C" void kernel_launch(void* const* d_in, const int* in_sizes, int n_in,
                              void* d_out, int out_size) {
    const float* fea = (const float*)d_in[0];
    const float* kp  = (const float*)d_in[1];
    float* out = (float*)d_out;
    (void)in_sizes; (void)n_in; (void)out_size;

    dim3 grid(NROI * 4 * 4);   // 1280 blocks: ROI x bin x channel-group
    dim3 block(128);           // 4 row-groups x 16 channels x 2 float4-depth-quads
    roi_align_25d_kernel<<<grid, block>>>(fea, kp, out);
}

// round 6
// speedup vs baseline: 2.1973x; 1.0179x over previous
#include <cuda_runtime.h>
#include <cuda_bf16.h>

// ROI align 2.5D — separable-weight formulation.
// fea: (B=16, C=64, H=128, W=128, D=8) f32, contiguous.
// keypoints: (16, 5, 3) f32.
// out: (16, 5, 64, 2, 2, 8) f32.
//
// Per (ROI, bin): out[c,d] = (1/(gh*gw)) * sum_y Wy[y] * sum_x Wx[x] * fea[b,c,y,x,d]
//
// R6: warp-per-channel layout. Lanes = 16 x-pixels x 2 depth-quads -> each
// warp-LDG is one contiguous 512B span (4-5 L1tex wavefronts vs 16 before).
// Each lane: fixed x, accumulate over y; Wx applied once after the loop;
// shfl_xor reduction over x. Second accumulator path covers x in [16, nx).

#define RB  16
#define RC  64
#define RH  128
#define RW  128
#define RD  8
#define NKP 5
#define NROI (RB * NKP)          // 80
#define CROP 16.0f               // H * 1/8
#define WSLOTS 32                // padded so Wx[x+16] (x<16) is always in-bounds
#define WPB 8                    // warps (channels) per block

__global__ __launch_bounds__(256)
void roi_align_25d_kernel(const float* __restrict__ fea,
                          const float* __restrict__ kp,
                          float* __restrict__ out) {
    const int blk = blockIdx.x;          // 2560 blocks: ROI x bin x cg
    const int cg  = blk & 7;             // channel group (8 ch)
    const int bin = (blk >> 3) & 3;      // ph*2 + pw
    const int n   = blk >> 5;            // ROI index 0..79
    const int ph  = bin >> 1;
    const int pw  = bin & 1;
    const int b   = n / NKP;

    __shared__ float Wx[WSLOTS], Wy[WSLOTS];
    __shared__ int   sBase[2];   // [0]=x0, [1]=y0
    __shared__ int   sCnt[2];    // [0]=nx, [1]=ny
    __shared__ int   sG[2];      // [0]=gw, [1]=gh

    const int t    = threadIdx.x;
    const int wid  = t >> 5;
    const int lane = t & 31;

    if (t < 2) {
        // t==0 -> x axis (uses pw), t==1 -> y axis (uses ph)
        float coord = kp[n * 3 + t] * 128.0f;
        float mn = fminf(fmaxf(coord - CROP, 0.0f), 127.0f);
        float mx = fminf(fmaxf(coord + CROP, 0.0f), 127.0f);
        float roi = fmaxf(mx - mn, 1.0f);
        float bin_sz = roi * 0.5f;                 // roi / P (P=2)
        int   g = (int)ceilf(bin_sz);              // ceil(roi/2), 1..16
        float step = bin_sz / (float)g;
        int   p = (t == 0) ? pw : ph;
        float start = mn + (float)p * bin_sz;

        float* Wp = (t == 0) ? Wx : Wy;
        #pragma unroll
        for (int i = 0; i < WSLOTS; i++) Wp[i] = 0.0f;

        // first sample defines the base index (samples are monotone in g)
        float s0 = start + 0.5f * step;
        int base = (int)floorf(fmaxf(s0, 0.0f));
        if (base > 127) base = 127;
        int maxc = base;

        for (int gi = 0; gi < g; gi++) {
            float s = start + ((float)gi + 0.5f) * step;
            if (s < -1.0f || s > 128.0f) continue;     // validity mask
            float c0 = fmaxf(s, 0.0f);
            int l0 = (int)floorf(c0);
            int lo, hi; float fr;
            if (l0 >= 127) { lo = 127; hi = 127; fr = 0.0f; }
            else           { lo = l0;  hi = l0 + 1; fr = c0 - (float)l0; }
            Wp[lo - base] += 1.0f - fr;
            Wp[hi - base] += fr;
            if (hi > maxc) maxc = hi;
        }
        sBase[t] = base;
        sCnt[t]  = maxc - base + 1;
        sG[t]    = g;
    }
    __syncthreads();

    const int x0 = sBase[0], nx = sCnt[0];
    const int y0 = sBase[1], ny = sCnt[1];
    const float inv = 1.0f / ((float)sG[0] * (float)sG[1]);

    const int c  = cg * WPB + wid;       // channel of this warp
    const int x  = lane >> 1;            // x-pixel within window, 0..15
    const int dq = lane & 1;             // which float4 of the 8-float depth

    const float4* __restrict__ fp = (const float4*)fea;

    // Per-lane weights; clamp OOW lanes to x=0 (weight is 0, load is L1 dup).
    const float wx1 = Wx[x];
    const int   xe1 = (x < nx) ? x : 0;
    const float wx2 = Wx[x + 16];                 // zero-padded -> safe
    const int   xe2 = (x + 16 < nx) ? x + 16 : 0;

    // float4 index: (((b*C + c)*H + y)*W + x)*2 + dq   (max ~33.5M, fits int)
    const int rowStride = RW * 2;
    int idx1 = (((b * RC + c) * RH + y0) * RW + x0 + xe1) * 2 + dq;
    int idx2 = (((b * RC + c) * RH + y0) * RW + x0 + xe2) * 2 + dq;

    float4 acc1 = make_float4(0.f, 0.f, 0.f, 0.f);
    float4 acc2 = make_float4(0.f, 0.f, 0.f, 0.f);

    if (nx <= 16) {
        #pragma unroll 4
        for (int iy = 0; iy < ny; iy++) {
            const float wy = Wy[iy];
            const float4 v = fp[idx1 + iy * rowStride];
            acc1.x += wy * v.x;  acc1.y += wy * v.y;
            acc1.z += wy * v.z;  acc1.w += wy * v.w;
        }
    } else {
        #pragma unroll 4
        for (int iy = 0; iy < ny; iy++) {
            const float wy = Wy[iy];
            const float4 v1 = fp[idx1 + iy * rowStride];
            const float4 v2 = fp[idx2 + iy * rowStride];
            acc1.x += wy * v1.x;  acc1.y += wy * v1.y;
            acc1.z += wy * v1.z;  acc1.w += wy * v1.w;
            acc2.x += wy * v2.x;  acc2.y += wy * v2.y;
            acc2.z += wy * v2.z;  acc2.w += wy * v2.w;
        }
    }

    float4 s;
    s.x = wx1 * acc1.x + wx2 * acc2.x;
    s.y = wx1 * acc1.y + wx2 * acc2.y;
    s.z = wx1 * acc1.z + wx2 * acc2.z;
    s.w = wx1 * acc1.w + wx2 * acc2.w;

    // Reduce over x (lane bits 1..4), keeping dq pairs separate.
    #pragma unroll
    for (int m = 2; m <= 16; m <<= 1) {
        s.x += __shfl_xor_sync(0xffffffffu, s.x, m);
        s.y += __shfl_xor_sync(0xffffffffu, s.y, m);
        s.z += __shfl_xor_sync(0xffffffffu, s.z, m);
        s.w += __shfl_xor_sync(0xffffffffu, s.w, m);
    }

    if (lane < 2) {
        s.x *= inv; s.y *= inv; s.z *= inv; s.w *= inv;
        // out: (NROI, C, 2, 2, 8) -> float4 index (((n*C+c)*2+ph)*2+pw)*2+dq
        float4* __restrict__ op = (float4*)out;
        op[(((n * RC + c) * 2 + ph) * 2 + pw) * 2 + dq] = s;
    }
}

extern "C" void kernel_launch(void* const* d_in, const int* in_sizes, int n_in,
                              void* d_out, int out_size) {
    const float* fea = (const float*)d_in[0];
    const float* kp  = (const float*)d_in[1];
    float* out = (float*)d_out;
    (void)in_sizes; (void)n_in; (void)out_size;

    dim3 grid(NROI * 4 * (RC / WPB));   // 2560 blocks: ROI x bin x channel-group
    dim3 block(32 * WPB);               // 8 warps = 8 channels
    roi_align_25d_kernel<<<grid, block>>>(fea, kp, out);
}